// round 17
// baseline (speedup 1.0000x reference)
#include <cuda_runtime.h>
#include <math.h>

// ---------------------------------------------------------------------------
// BalancedFrequencyAttention, collapsed form (see R2 derivation):
//   gap[b,c] = sum_{h,n} x[b,c,h,n] * w(h,n)
//   w(h,n)   = c0 + [h>=80] * (0.4/48000) * g_{(h-80)%3}(n),  period-12 in n
//   att      = sigmoid(gap @ w1^T @ w2^T);  out = x * att[:,:,None,None]
//
// R16 = R15 + L2 tail-reuse across kernels:
//   - reduce reads x with DEFAULT policy (allocates in L2; last ~126MB of x
//     stays resident at kernel end)
//   - scale runs in REVERSED block order, so its first waves re-read exactly
//     the channels reduce touched last -> L2 hits instead of DRAM
//   - scale writes stay __stcs (evict-first) to protect the resident x tail
// ---------------------------------------------------------------------------

#define N_CH        1024      // B*C
#define Q_PER_CH    24000     // 200*480/4 float4 per channel
#define BLKS_PER_CH 10
#define TOTAL_Q4    (N_CH * Q_PER_CH)        // 24,576,000 = 48000 * 512
#define SCALE_BLKS  (TOTAL_Q4 / 512)         // 48000

__device__ float d_part[N_CH * BLKS_PER_CH];
__device__ float d_att[N_CH];

// ---- Kernel 1: weighted reduction, constant-register weights, 20-row units ---
__global__ __launch_bounds__(256, 8) void reduce_kernel(const float4* __restrict__ x) {
    const float c0  = 8.838834764831843e-06f;   // 0.6/sqrt(2)/48000
    const float inv = 8.333333333333334e-06f;   // 0.4/48000
    const float PI  = 3.14159265358979323846f;

    const int blk = blockIdx.x;
    const int ch  = blk / BLKS_PER_CH;
    const int s   = blk - ch * BLKS_PER_CH;

    const int t    = threadIdx.x;
    const int c4   = t & 127;          // float4 column (0..119 active)
    const int r    = t >> 7;           // row-within-pair (0/1)
    const bool act = (c4 < 120);

    // Per-thread constant weight (computed once).
    float4 w = make_float4(c0, c0, c0, c0);
    if (s >= 4) {
        const int k  = (s - 4) % 3;    // high class (h-80)%3 == k, fixed
        const int n0 = c4 << 2;
        float g[4];
        #pragma unroll
        for (int e = 0; e < 4; e++) {
            float a = (float)(2 * ((n0 + e) % 12) + 1);
            float gv;
            if (k == 0)      gv = cosf(a * (PI / 12.f)) + cosf(a * (PI / 3.f));
            else if (k == 1) gv = cosf(a * (PI / 6.f))  + cosf(a * (5.f * PI / 12.f));
            else             gv = cosf(a * (PI / 4.f));
            g[e] = c0 + inv * gv;
        }
        w = make_float4(g[0], g[1], g[2], g[3]);
    }

    size_t base; int stride;
    if (s < 4) {                           // low: contiguous rows 20s .. 20s+19
        base   = (size_t)ch * Q_PER_CH + (size_t)(20 * s + r) * 120 + c4;
        stride = 240;                      // 2 rows per iteration
    } else {                               // high: class k, half index
        const int k    = (s - 4) % 3;
        const int half = (s - 4) / 3;      // m in [20*half, 20*half+20)
        base   = (size_t)ch * Q_PER_CH
               + (size_t)(80 + k + 60 * half + 3 * r) * 120 + c4;
        stride = 720;                      // 2 strided rows (6 physical rows)
    }

    float acc0 = 0.f, acc1 = 0.f;
    if (act) {
        const float4* p = x + base;
        #pragma unroll 5
        for (int i = 0; i < 10; i++) {     // 20 rows per block (2 per iter)
            float4 v = *p;                 // DEFAULT policy: allocate in L2
            p += stride;
            acc0 += v.x * w.x + v.y * w.y;
            acc1 += v.z * w.z + v.w * w.w;
        }
    }
    float acc = acc0 + acc1;

    __shared__ float wsum[8];
    #pragma unroll
    for (int o = 16; o; o >>= 1) acc += __shfl_xor_sync(0xffffffffu, acc, o);
    if ((t & 31) == 0) wsum[t >> 5] = acc;
    __syncthreads();
    if (t < 8) {
        float v = wsum[t];
        #pragma unroll
        for (int o = 4; o; o >>= 1) v += __shfl_xor_sync(0xffu, v, o);
        if (t == 0) { d_part[blk] = v; __threadfence(); }
    }
    __syncthreads();
    cudaTriggerProgrammaticLaunchCompletion();   // release mlp at last store
}

// ---- Kernel 2: MLP, one block per batch b (8 blocks, PDL) --------------------
__global__ __launch_bounds__(256) void mlp_kernel(const float* __restrict__ w1,
                                                  const float* __restrict__ w2) {
    __shared__ float sg[128];        // gap for this batch
    __shared__ float sw1[32][129];   // padded: conflict-free column reads
    __shared__ float sw2[128][33];
    __shared__ float st1[32];
    const int tid = threadIdx.x;
    const int b   = blockIdx.x;      // batch index, 0..7

    // Independent of d_part: overlaps reduce_kernel execution.
    for (int i = tid; i < 4096; i += 256) {
        sw1[i >> 7][i & 127] = w1[i];   // w1[j][c], j<32, c<128
        sw2[i >> 5][i & 31]  = w2[i];   // w2[c][j], c<128, j<32
    }

    cudaGridDependencySynchronize();    // wait for reduce_kernel's d_part

    // Fold 10 partials for this batch's 128 channels.
    if (tid < 128) {
        const float* p = &d_part[(b * 128 + tid) * BLKS_PER_CH];
        float v = 0.f;
        #pragma unroll
        for (int q = 0; q < BLKS_PER_CH; q++) v += p[q];
        sg[tid] = v;
    }
    __syncthreads();

    // Stage 1: t1[j] = sum_c gap[c] * w1[j][c]  — 8 threads per j, 16 c each.
    {
        int j = tid >> 3, part = tid & 7;     // j<32, part<8
        float s = 0.f;
        #pragma unroll
        for (int c = part * 16; c < part * 16 + 16; c++) s += sg[c] * sw1[j][c];
        #pragma unroll
        for (int o = 4; o; o >>= 1) s += __shfl_xor_sync(0xffffffffu, s, o);
        if (part == 0) st1[j] = s;
    }
    __syncthreads();

    // Stage 2: att[c] = sigmoid(sum_j t1[j] * w2[c][j])  — threads 0..127.
    if (tid < 128) {
        float z = 0.f;
        #pragma unroll
        for (int jj = 0; jj < 32; jj++) z += st1[jj] * sw2[tid][jj];
        d_att[b * 128 + tid] = 1.f / (1.f + expf(-z));
    }
    __threadfence();
    __syncthreads();
    cudaTriggerProgrammaticLaunchCompletion();   // release scale at d_att store
}

// ---- Kernel 3: scale, 2 float4/thread, REVERSED order (L2 tail reuse) --------
__global__ __launch_bounds__(256) void scale_kernel(const float4* __restrict__ x,
                                                    float4* __restrict__ out) {
    // Reverse block order: first waves touch the channels reduce read LAST,
    // which are still L2-resident.
    unsigned rblk = (unsigned)(SCALE_BLKS - 1) - blockIdx.x;
    unsigned i0 = rblk * 512u + threadIdx.x;          // < 24,576,000 always
    unsigned i1 = i0 + 256u;
    float4 v0 = x[i0];                   // default policy: may HIT L2
    float4 v1 = x[i1];
    unsigned c0 = i0 / (unsigned)Q_PER_CH;
    unsigned c1 = i1 / (unsigned)Q_PER_CH;

    cudaGridDependencySynchronize();     // wait only for d_att

    float a0 = d_att[c0];
    float a1 = d_att[c1];
    v0.x *= a0; v0.y *= a0; v0.z *= a0; v0.w *= a0;
    v1.x *= a1; v1.y *= a1; v1.z *= a1; v1.w *= a1;
    __stcs(&out[i0], v0);                // evict-first: protect resident x
    __stcs(&out[i1], v1);
}

// ---- Launch ------------------------------------------------------------------
extern "C" void kernel_launch(void* const* d_in, const int* in_sizes, int n_in,
                              void* d_out, int out_size) {
    const float* x  = (const float*)d_in[0];
    const float* w1 = (const float*)d_in[1];
    const float* w2 = (const float*)d_in[2];
    float* out = (float*)d_out;

    reduce_kernel<<<N_CH * BLKS_PER_CH, 256>>>(reinterpret_cast<const float4*>(x));

    cudaLaunchAttribute attr[1];
    attr[0].id = cudaLaunchAttributeProgrammaticStreamSerialization;
    attr[0].val.programmaticStreamSerializationAllowed = 1;

    {   // mlp: 8 blocks (one per batch), PDL-overlapped with reduce
        cudaLaunchConfig_t cfg = {};
        cfg.gridDim = dim3(8, 1, 1);
        cfg.blockDim = dim3(256, 1, 1);
        cfg.dynamicSmemBytes = 0;
        cfg.stream = 0;
        cfg.attrs = attr;
        cfg.numAttrs = 1;
        cudaLaunchKernelEx(&cfg, mlp_kernel, w1, w2);
    }
    {   // scale: PDL-overlapped with mlp, reversed traversal
        cudaLaunchConfig_t cfg = {};
        cfg.gridDim = dim3(SCALE_BLKS, 1, 1);         // 48000 blocks, no tail
        cfg.blockDim = dim3(256, 1, 1);
        cfg.dynamicSmemBytes = 0;
        cfg.stream = 0;
        cfg.attrs = attr;
        cfg.numAttrs = 1;
        cudaLaunchKernelEx(&cfg, scale_kernel,
                           reinterpret_cast<const float4*>(x),
                           reinterpret_cast<float4*>(out));
    }
}